// round 15
// baseline (speedup 1.0000x reference)
#include <cuda_runtime.h>
#include <stdint.h>

namespace {
constexpr int N   = 512;
constexpr int D   = 64;
constexpr int C   = 32;
constexpr int HID = 128;
constexpr int NH  = 8;
constexpr int HD  = 16;
constexpr float SCALE_EX2 = 0.25f * 1.4426950408889634f;  // head_dim^-0.5 * log2(e)
constexpr float NEG_BIAS  = -8.0f;                         // fp16 overflow guard (cancels)
constexpr int THREADS = 512;
constexpr int NBT = 96;

// smem byte offsets (no Q region: Q lives in registers)
constexpr int XSTRIDE = 144;                   // x fp16 row stride — ldm conflict-free
constexpr int OFF_X  = 0;                      // x fp16 [512][72]       = 73728
constexpr int OFF_K  = 73728;                  // K fp16 [512][24] (48B) = 24576
constexpr int OFF_V  = OFF_K + 24576;          // V fp16 [512][24]
constexpr int OFF_W  = OFF_V + 24576;          // W fp16 [48][72] (144B) = 6912
constexpr int SMEM_BYTES = OFF_W + 6912;       // 129792

// overlays: x dead after projection; K dead after attention
constexpr int OFF_SX   = 0;                    // sx fp16 [512][24] (48B) = 24576
constexpr int OFF_CLS  = 24576;                // cls fp16 [32][520] (1040B) = 33280
constexpr int OFF_PART = OFF_K;                // pooling partials f32 [4][32][16] = 8192
constexpr uint32_t ONES2 = 0x3C003C00u;
}

__device__ __forceinline__ uint32_t s2u(const void* p) {
    uint32_t a;
    asm("{ .reg .u64 t; cvta.to.shared.u64 t, %1; cvt.u32.u64 %0, t; }" : "=r"(a) : "l"(p));
    return a;
}
__device__ __forceinline__ float fast_ex2(float x) {
    float r; asm("ex2.approx.f32 %0, %1;" : "=f"(r) : "f"(x)); return r;
}
__device__ __forceinline__ uint16_t h_of(float v) {
    uint16_t r; asm("cvt.rn.f16.f32 %0, %1;" : "=h"(r) : "f"(v)); return r;
}
__device__ __forceinline__ uint32_t h2_of(float lo, float hi) {
    uint32_t r; asm("cvt.rn.f16x2.f32 %0, %1, %2;" : "=r"(r) : "f"(hi), "f"(lo)); return r;
}
__device__ __forceinline__ uint32_t h2sat(float lo, float hi) {
    uint32_t r;
    asm("cvt.rn.satfinite.f16x2.f32 %0, %1, %2;" : "=r"(r) : "f"(hi), "f"(lo));
    return r;
}
__device__ __forceinline__ void ldm_x4(uint32_t r[4], uint32_t addr) {
    asm volatile("ldmatrix.sync.aligned.m8n8.x4.shared.b16 {%0,%1,%2,%3}, [%4];"
                 : "=r"(r[0]), "=r"(r[1]), "=r"(r[2]), "=r"(r[3]) : "r"(addr));
}
__device__ __forceinline__ void ldm_x4t(uint32_t r[4], uint32_t addr) {
    asm volatile("ldmatrix.sync.aligned.m8n8.x4.trans.shared.b16 {%0,%1,%2,%3}, [%4];"
                 : "=r"(r[0]), "=r"(r[1]), "=r"(r[2]), "=r"(r[3]) : "r"(addr));
}
__device__ __forceinline__ void ldm_x2t(uint32_t& r0, uint32_t& r1, uint32_t addr) {
    asm volatile("ldmatrix.sync.aligned.m8n8.x2.trans.shared.b16 {%0,%1}, [%2];"
                 : "=r"(r0), "=r"(r1) : "r"(addr));
}
__device__ __forceinline__ void mma16816(float* d,
                                         const uint32_t* a, uint32_t b0, uint32_t b1,
                                         float c0, float c1, float c2, float c3) {
    asm volatile("mma.sync.aligned.m16n8k16.row.col.f32.f16.f16.f32 "
                 "{%0,%1,%2,%3}, {%4,%5,%6,%7}, {%8,%9}, {%10,%11,%12,%13};"
                 : "=f"(d[0]), "=f"(d[1]), "=f"(d[2]), "=f"(d[3])
                 : "r"(a[0]), "r"(a[1]), "r"(a[2]), "r"(a[3]), "r"(b0), "r"(b1),
                   "f"(c0), "f"(c1), "f"(c2), "f"(c3));
}

__global__ __launch_bounds__(THREADS, 1)
void spatial_attn_mma5(const float* __restrict__ x, const float* __restrict__ cls,
                       const float* __restrict__ Wq, const float* __restrict__ Wk,
                       const float* __restrict__ Wv, float* __restrict__ out) {
    extern __shared__ char smem[];
    const uint32_t sbase = s2u(smem);
    float* smf = reinterpret_cast<float*>(smem);

    const int blk = blockIdx.x, h = blk & (NH - 1), bt = blk >> 3;
    const float* xg   = x + (size_t)bt * N * D;
    const float* clsg = cls + (size_t)bt * C * N;
    const int tid = threadIdx.x, lane = tid & 31, wid = tid >> 5;   // 16 warps

    // ---- stage x -> fp16 [512][72] and this head's W -> fp16 [48][72] ----
    for (int i = tid; i < N * D / 4; i += THREADS) {
        const int row = i >> 4, c4 = i & 15;
        const float4 v4 = *reinterpret_cast<const float4*>(xg + row * D + c4 * 4);
        *reinterpret_cast<uint2*>(smem + OFF_X + row * XSTRIDE + c4 * 8) =
            make_uint2(h2_of(v4.x, v4.y), h2_of(v4.z, v4.w));
    }
    for (int idx = tid; idx < 3 * HD * D; idx += THREADS) {
        const int kind = idx >> 10, rem = idx & 1023, e = rem >> 6, d = rem & 63;
        const float* Ws = (kind == 0) ? Wq : (kind == 1) ? Wk : Wv;
        *reinterpret_cast<uint16_t*>(smem + OFF_W + (kind * HD + e) * XSTRIDE + d * 2) =
            h_of(Ws[(h * HD + e) * D + d]);
    }
    __syncthreads();

    uint32_t qa[2][4];   // Q A-fragments, built directly from projection accumulators

    // ---- projection via mma: warp owns x rows [wid*32, wid*32+32) ----
    {
        float acc[3][2][2][4];
        #pragma unroll
        for (int k = 0; k < 3; k++)
            #pragma unroll
            for (int mt = 0; mt < 2; mt++)
                #pragma unroll
                for (int nt = 0; nt < 2; nt++)
                    #pragma unroll
                    for (int j = 0; j < 4; j++) acc[k][mt][nt][j] = 0.f;

        const uint32_t arow = (uint32_t)(wid * 32 + (lane & 15));
        const uint32_t ainc = (uint32_t)((lane >> 4) * 16);
        const uint32_t brow = (uint32_t)((lane & 7) + ((lane & 16) ? 8 : 0));
        const uint32_t binc = (uint32_t)((lane & 8) ? 16 : 0);

        #pragma unroll
        for (int j = 0; j < 4; j++) {
            uint32_t ax[2][4];
            ldm_x4(ax[0], sbase + OFF_X + arow * XSTRIDE + ainc + (uint32_t)j * 32u);
            ldm_x4(ax[1], sbase + OFF_X + (arow + 16) * XSTRIDE + ainc + (uint32_t)j * 32u);
            #pragma unroll
            for (int kind = 0; kind < 3; kind++) {
                uint32_t wf[4];
                ldm_x4(wf, sbase + OFF_W + ((uint32_t)kind * 16u + brow) * XSTRIDE + binc
                             + (uint32_t)j * 32u);
                #pragma unroll
                for (int mt = 0; mt < 2; mt++) {
                    mma16816(acc[kind][mt][0], ax[mt], wf[0], wf[1],
                             acc[kind][mt][0][0], acc[kind][mt][0][1],
                             acc[kind][mt][0][2], acc[kind][mt][0][3]);
                    mma16816(acc[kind][mt][1], ax[mt], wf[2], wf[3],
                             acc[kind][mt][1][0], acc[kind][mt][1][1],
                             acc[kind][mt][1][2], acc[kind][mt][1][3]);
                }
            }
        }

        // Q -> registers: C-pair (c0,c1)=(g,cq..cq+1), (c2,c3)=(g+8,...) maps to A-frag a0..a3
        #pragma unroll
        for (int mt = 0; mt < 2; mt++) {
            qa[mt][0] = h2_of(acc[0][mt][0][0] * SCALE_EX2, acc[0][mt][0][1] * SCALE_EX2);
            qa[mt][1] = h2_of(acc[0][mt][0][2] * SCALE_EX2, acc[0][mt][0][3] * SCALE_EX2);
            qa[mt][2] = h2_of(acc[0][mt][1][0] * SCALE_EX2, acc[0][mt][1][1] * SCALE_EX2);
            qa[mt][3] = h2_of(acc[0][mt][1][2] * SCALE_EX2, acc[0][mt][1][3] * SCALE_EX2);
        }

        // K/V -> smem fp16, stride 48B
        const int g = lane >> 2, cq = (lane & 3) * 2;
        #pragma unroll
        for (int kind = 1; kind < 3; kind++) {
            char* base = smem + (kind == 1 ? OFF_K : OFF_V);
            #pragma unroll
            for (int mt = 0; mt < 2; mt++) {
                #pragma unroll
                for (int nt = 0; nt < 2; nt++) {
                    const int row = wid * 32 + mt * 16 + g;
                    const int eoff = (nt * 8 + cq) * 2;
                    *reinterpret_cast<uint32_t*>(base + row * 48 + eoff) =
                        h2_of(acc[kind][mt][nt][0], acc[kind][mt][nt][1]);
                    *reinterpret_cast<uint32_t*>(base + (row + 8) * 48 + eoff) =
                        h2_of(acc[kind][mt][nt][2], acc[kind][mt][nt][3]);
                }
            }
        }
    }
    __syncthreads();

    // ---- stage cls -> fp16 [32][520] (overlaps with attention) ----
    for (int i = tid; i < C * N / 4; i += THREADS) {
        const int c = i >> 7, n4 = i & 127;
        const float4 v4 = *reinterpret_cast<const float4*>(clsg + c * N + n4 * 4);
        *reinterpret_cast<uint2*>(smem + OFF_CLS + c * 1040 + n4 * 8) =
            make_uint2(h2_of(v4.x, v4.y), h2_of(v4.z, v4.w));
    }

    // ---- flash attention, software-pipelined, R12 numerics (fp32 ex2 + satfinite) ----
    {
        const int rb = wid * 32;
        float O[2][2][4], R[2][4];
        #pragma unroll
        for (int mt = 0; mt < 2; mt++) {
            #pragma unroll
            for (int nn = 0; nn < 2; nn++)
                #pragma unroll
                for (int j = 0; j < 4; j++) O[mt][nn][j] = 0.f;
            #pragma unroll
            for (int j = 0; j < 4; j++) R[mt][j] = 0.f;
        }

        const uint32_t koff = (uint32_t)(((lane & 7) + ((lane & 16) ? 8 : 0)) * 48
                                         + ((lane & 8) ? 16 : 0));
        const uint32_t voff = (uint32_t)(((lane & 7) + ((lane & 8) ? 8 : 0)) * 48
                                         + ((lane & 16) ? 16 : 0));

        uint32_t kf[2][4], vf[2][4], pa[2][4];
        float s[2][2][4];

        ldm_x4 (kf[0], sbase + OFF_K + koff);
        ldm_x4t(vf[0], sbase + OFF_V + voff);
        ldm_x4 (kf[1], sbase + OFF_K + 768u + koff);
        ldm_x4t(vf[1], sbase + OFF_V + 768u + voff);

        // kb=0: S + pa only
        mma16816(s[0][0], qa[0], kf[0][0], kf[0][1], NEG_BIAS, NEG_BIAS, NEG_BIAS, NEG_BIAS);
        mma16816(s[0][1], qa[0], kf[0][2], kf[0][3], NEG_BIAS, NEG_BIAS, NEG_BIAS, NEG_BIAS);
        mma16816(s[1][0], qa[1], kf[0][0], kf[0][1], NEG_BIAS, NEG_BIAS, NEG_BIAS, NEG_BIAS);
        mma16816(s[1][1], qa[1], kf[0][2], kf[0][3], NEG_BIAS, NEG_BIAS, NEG_BIAS, NEG_BIAS);
        #pragma unroll
        for (int mt = 0; mt < 2; mt++) {
            pa[mt][0] = h2sat(fast_ex2(s[mt][0][0]), fast_ex2(s[mt][0][1]));
            pa[mt][1] = h2sat(fast_ex2(s[mt][0][2]), fast_ex2(s[mt][0][3]));
            pa[mt][2] = h2sat(fast_ex2(s[mt][1][0]), fast_ex2(s[mt][1][1]));
            pa[mt][3] = h2sat(fast_ex2(s[mt][1][2]), fast_ex2(s[mt][1][3]));
        }

        #pragma unroll 2
        for (int kb = 1; kb < 32; kb++) {
            const int cur = kb & 1, prv = cur ^ 1;

            mma16816(s[0][0], qa[0], kf[cur][0], kf[cur][1],
                     NEG_BIAS, NEG_BIAS, NEG_BIAS, NEG_BIAS);
            mma16816(s[0][1], qa[0], kf[cur][2], kf[cur][3],
                     NEG_BIAS, NEG_BIAS, NEG_BIAS, NEG_BIAS);
            mma16816(s[1][0], qa[1], kf[cur][0], kf[cur][1],
                     NEG_BIAS, NEG_BIAS, NEG_BIAS, NEG_BIAS);
            mma16816(s[1][1], qa[1], kf[cur][2], kf[cur][3],
                     NEG_BIAS, NEG_BIAS, NEG_BIAS, NEG_BIAS);

            #pragma unroll
            for (int mt = 0; mt < 2; mt++) {
                mma16816(O[mt][0], pa[mt], vf[prv][0], vf[prv][1],
                         O[mt][0][0], O[mt][0][1], O[mt][0][2], O[mt][0][3]);
                mma16816(O[mt][1], pa[mt], vf[prv][2], vf[prv][3],
                         O[mt][1][0], O[mt][1][1], O[mt][1][2], O[mt][1][3]);
                mma16816(R[mt], pa[mt], ONES2, ONES2,
                         R[mt][0], R[mt][1], R[mt][2], R[mt][3]);
            }

            if (kb < 31) {
                ldm_x4 (kf[prv], sbase + OFF_K + (uint32_t)(kb + 1) * 768u + koff);
                ldm_x4t(vf[prv], sbase + OFF_V + (uint32_t)(kb + 1) * 768u + voff);
            }

            #pragma unroll
            for (int mt = 0; mt < 2; mt++) {
                pa[mt][0] = h2sat(fast_ex2(s[mt][0][0]), fast_ex2(s[mt][0][1]));
                pa[mt][1] = h2sat(fast_ex2(s[mt][0][2]), fast_ex2(s[mt][0][3]));
                pa[mt][2] = h2sat(fast_ex2(s[mt][1][0]), fast_ex2(s[mt][1][1]));
                pa[mt][3] = h2sat(fast_ex2(s[mt][1][2]), fast_ex2(s[mt][1][3]));
            }
        }

        // drain: O/R for kb=31 (vf[1] holds block 31)
        #pragma unroll
        for (int mt = 0; mt < 2; mt++) {
            mma16816(O[mt][0], pa[mt], vf[1][0], vf[1][1],
                     O[mt][0][0], O[mt][0][1], O[mt][0][2], O[mt][0][3]);
            mma16816(O[mt][1], pa[mt], vf[1][2], vf[1][3],
                     O[mt][1][0], O[mt][1][1], O[mt][1][2], O[mt][1][3]);
            mma16816(R[mt], pa[mt], ONES2, ONES2,
                     R[mt][0], R[mt][1], R[mt][2], R[mt][3]);
        }

        // normalize + write sx fp16 [512][24] (48B stride) into dead x region
        const int g = lane >> 2, cq = (lane & 3) * 2;
        #pragma unroll
        for (int mt = 0; mt < 2; mt++) {
            const float inv0 = __frcp_rn(R[mt][0]);
            const float inv1 = __frcp_rn(R[mt][2]);
            const int row0 = rb + mt * 16 + g, row1 = row0 + 8;
            #pragma unroll
            for (int nn = 0; nn < 2; nn++) {
                const int eoff = (nn * 8 + cq) * 2;
                *reinterpret_cast<uint32_t*>(smem + OFF_SX + row0 * 48 + eoff) =
                    h2_of(O[mt][nn][0] * inv0, O[mt][nn][1] * inv0);
                *reinterpret_cast<uint32_t*>(smem + OFF_SX + row1 * 48 + eoff) =
                    h2_of(O[mt][nn][2] * inv1, O[mt][nn][3] * inv1);
            }
        }
    }
    __syncthreads();

    // ---- pooling via mma on ALL 16 warps: warp = (mt, nt, kgroup) ----
    {
        const int mt = wid & 1, nt = (wid >> 1) & 1, kg = wid >> 2;
        float acc[4] = {0.f, 0.f, 0.f, 0.f};
        const uint32_t aaddr = sbase + OFF_CLS
            + (uint32_t)(mt * 16 + (lane & 15)) * 1040u + (uint32_t)(lane >> 4) * 16u;
        const uint32_t brow = (uint32_t)((lane & 7) + ((lane & 8) ? 8 : 0));

        #pragma unroll
        for (int jj = 0; jj < 8; jj++) {
            const int j = kg * 8 + jj;
            uint32_t af[4];
            ldm_x4(af, aaddr + (uint32_t)j * 32u);
            uint32_t b0, b1;
            ldm_x2t(b0, b1, sbase + OFF_SX + ((uint32_t)j * 16u + brow) * 48u
                              + (uint32_t)nt * 16u);
            mma16816(acc, af, b0, b1, acc[0], acc[1], acc[2], acc[3]);
        }

        const int g = lane >> 2, cq = (lane & 3) * 2;
        float* part = smf + OFF_PART / 4;
        const int c0 = mt * 16 + g, d = nt * 8 + cq;
        *reinterpret_cast<float2*>(part + kg * 512 + c0 * 16 + d)       =
            make_float2(acc[0], acc[1]);
        *reinterpret_cast<float2*>(part + kg * 512 + (c0 + 8) * 16 + d) =
            make_float2(acc[2], acc[3]);
    }
    __syncthreads();

    // ---- final reduce: 512 threads, one (c,d) each ----
    {
        const int c = tid >> 4, d = tid & 15;
        const float* part = smf + OFF_PART / 4;
        const float v = (part[0 * 512 + c * 16 + d] + part[1 * 512 + c * 16 + d])
                      + (part[2 * 512 + c * 16 + d] + part[3 * 512 + c * 16 + d]);
        out[((size_t)bt * C + c) * HID + h * HD + d] = v;
    }
}

extern "C" void kernel_launch(void* const* d_in, const int* in_sizes, int n_in,
                              void* d_out, int out_size) {
    const float* x   = (const float*)d_in[0];
    const float* cls = (const float*)d_in[1];
    const float* Wq  = (const float*)d_in[2];
    const float* Wk  = (const float*)d_in[3];
    const float* Wv  = (const float*)d_in[4];
    float* out = (float*)d_out;

    cudaFuncSetAttribute(spatial_attn_mma5, cudaFuncAttributeMaxDynamicSharedMemorySize,
                         SMEM_BYTES);
    spatial_attn_mma5<<<NBT * NH, THREADS, SMEM_BYTES>>>(x, cls, Wq, Wk, Wv, out);
}

// round 16
// speedup vs baseline: 1.2906x; 1.2906x over previous
#include <cuda_runtime.h>
#include <stdint.h>

namespace {
constexpr int N   = 512;
constexpr int D   = 64;
constexpr int C   = 32;
constexpr int HID = 128;
constexpr int NH  = 8;
constexpr int HD  = 16;
constexpr float SCALE_EX2 = 0.25f * 1.4426950408889634f;  // head_dim^-0.5 * log2(e)
constexpr float NEG_BIAS  = -8.0f;                         // fp16 overflow guard (cancels)
constexpr int THREADS = 256;
constexpr int NBT = 96;

// smem layout (88 KB -> 2 CTAs/SM)
constexpr int OFF_X = 0;          // x fp16, 256 rows x 128B, XOR-swizzled (per pass) = 32768
constexpr int OFF_K = 32768;      // K fp16 [512][24] (48B rows) = 24576
constexpr int OFF_V = 57344;      // V fp16 [512][24]            = 24576
constexpr int OFF_W = 81920;      // W fp16 [48] x 128B swizzled = 6144
constexpr int SMEM_BYTES = 88064;

// overlays: x dead after projection; K/V dead after attention
constexpr int OFF_SX   = 0;       // sx fp16 [512][24] (48B) = 24576
constexpr int OFF_PART = 24576;   // pooling partials f32 [2][32][16] = 4096
constexpr int OFF_CLS  = OFF_K;   // cls fp16 [32][520] (1040B rows) = 33280 <= 49152
constexpr uint32_t ONES2 = 0x3C003C00u;
}

__device__ __forceinline__ uint32_t s2u(const void* p) {
    uint32_t a;
    asm("{ .reg .u64 t; cvta.to.shared.u64 t, %1; cvt.u32.u64 %0, t; }" : "=r"(a) : "l"(p));
    return a;
}
__device__ __forceinline__ float fast_ex2(float x) {
    float r; asm("ex2.approx.f32 %0, %1;" : "=f"(r) : "f"(x)); return r;
}
__device__ __forceinline__ uint16_t h_of(float v) {
    uint16_t r; asm("cvt.rn.f16.f32 %0, %1;" : "=h"(r) : "f"(v)); return r;
}
__device__ __forceinline__ uint32_t h2_of(float lo, float hi) {
    uint32_t r; asm("cvt.rn.f16x2.f32 %0, %1, %2;" : "=r"(r) : "f"(hi), "f"(lo)); return r;
}
__device__ __forceinline__ uint32_t h2sat(float lo, float hi) {
    uint32_t r;
    asm("cvt.rn.satfinite.f16x2.f32 %0, %1, %2;" : "=r"(r) : "f"(hi), "f"(lo));
    return r;
}
__device__ __forceinline__ void ldm_x4(uint32_t r[4], uint32_t addr) {
    asm volatile("ldmatrix.sync.aligned.m8n8.x4.shared.b16 {%0,%1,%2,%3}, [%4];"
                 : "=r"(r[0]), "=r"(r[1]), "=r"(r[2]), "=r"(r[3]) : "r"(addr));
}
__device__ __forceinline__ void ldm_x4t(uint32_t r[4], uint32_t addr) {
    asm volatile("ldmatrix.sync.aligned.m8n8.x4.trans.shared.b16 {%0,%1,%2,%3}, [%4];"
                 : "=r"(r[0]), "=r"(r[1]), "=r"(r[2]), "=r"(r[3]) : "r"(addr));
}
__device__ __forceinline__ void ldm_x2t(uint32_t& r0, uint32_t& r1, uint32_t addr) {
    asm volatile("ldmatrix.sync.aligned.m8n8.x2.trans.shared.b16 {%0,%1}, [%2];"
                 : "=r"(r0), "=r"(r1) : "r"(addr));
}
__device__ __forceinline__ void mma16816(float* d,
                                         const uint32_t* a, uint32_t b0, uint32_t b1,
                                         float c0, float c1, float c2, float c3) {
    asm volatile("mma.sync.aligned.m16n8k16.row.col.f32.f16.f16.f32 "
                 "{%0,%1,%2,%3}, {%4,%5,%6,%7}, {%8,%9}, {%10,%11,%12,%13};"
                 : "=f"(d[0]), "=f"(d[1]), "=f"(d[2]), "=f"(d[3])
                 : "r"(a[0]), "r"(a[1]), "r"(a[2]), "r"(a[3]), "r"(b0), "r"(b1),
                   "f"(c0), "f"(c1), "f"(c2), "f"(c3));
}

__global__ __launch_bounds__(THREADS, 2)
void spatial_attn_mma6(const float* __restrict__ x, const float* __restrict__ cls,
                       const float* __restrict__ Wq, const float* __restrict__ Wk,
                       const float* __restrict__ Wv, float* __restrict__ out) {
    extern __shared__ char smem[];
    const uint32_t sbase = s2u(smem);
    float* smf = reinterpret_cast<float*>(smem);

    const int blk = blockIdx.x, h = blk & (NH - 1), bt = blk >> 3;
    const float* xg   = x + (size_t)bt * N * D;
    const float* clsg = cls + (size_t)bt * C * N;
    const int tid = threadIdx.x, lane = tid & 31, wid = tid >> 5;   // 8 warps

    // ---- stage this head's W -> fp16, 128B swizzled rows (once) ----
    for (int idx = tid; idx < 3 * HD * D; idx += THREADS) {         // 12 iters
        const int kind = idx >> 10, rem = idx & 1023, e = rem >> 6, d = rem & 63;
        const float* Ws = (kind == 0) ? Wq : (kind == 1) ? Wk : Wv;
        const int r = kind * HD + e;
        *reinterpret_cast<uint16_t*>(smem + OFF_W + r * 128
            + (((d >> 3) ^ (r & 7)) * 16) + (d & 7) * 2) = h_of(Ws[(h * HD + e) * D + d]);
    }

    uint32_t qa[4][4];   // Q A-fragments for this warp's 4 m16 tiles (built in-register)

    // ---- projection: two passes of 256 rows; warp owns 32 rows per pass ----
    #pragma unroll
    for (int p = 0; p < 2; p++) {
        if (p) __syncthreads();   // protect X reuse
        const float* xr = xg + p * 256 * D;
        for (int i = tid; i < 256 * 8; i += THREADS) {              // 8 iters, 16B chunks
            const int row = i >> 3, j = i & 7;
            const float4 a = *reinterpret_cast<const float4*>(xr + row * D + j * 8);
            const float4 b = *reinterpret_cast<const float4*>(xr + row * D + j * 8 + 4);
            uint4 u;
            u.x = h2_of(a.x, a.y); u.y = h2_of(a.z, a.w);
            u.z = h2_of(b.x, b.y); u.w = h2_of(b.z, b.w);
            *reinterpret_cast<uint4*>(smem + OFF_X + row * 128
                                      + ((j ^ (row & 7)) * 16)) = u;
        }
        __syncthreads();

        float acc[3][2][2][4];
        #pragma unroll
        for (int k = 0; k < 3; k++)
            #pragma unroll
            for (int mt = 0; mt < 2; mt++)
                #pragma unroll
                for (int nt = 0; nt < 2; nt++)
                    #pragma unroll
                    for (int j = 0; j < 4; j++) acc[k][mt][nt][j] = 0.f;

        const int arow0 = wid * 32 + (lane & 15);
        const int kq    = lane >> 4;                 // A chunk half
        const int brow  = (lane & 7) + ((lane & 16) ? 8 : 0);
        const int bhalf = (lane & 8) ? 1 : 0;

        #pragma unroll
        for (int j = 0; j < 4; j++) {
            uint32_t ax[2][4];
            #pragma unroll
            for (int mt = 0; mt < 2; mt++) {
                const int row = arow0 + mt * 16;
                const int ch  = 2 * j + kq;
                ldm_x4(ax[mt], sbase + OFF_X + (uint32_t)(row * 128
                             + ((ch ^ (row & 7)) * 16)));
            }
            #pragma unroll
            for (int kind = 0; kind < 3; kind++) {
                const int r  = kind * 16 + brow;
                const int ch = 2 * j + bhalf;
                uint32_t wf[4];
                ldm_x4(wf, sbase + OFF_W + (uint32_t)(r * 128 + ((ch ^ (r & 7)) * 16)));
                #pragma unroll
                for (int mt = 0; mt < 2; mt++) {
                    mma16816(acc[kind][mt][0], ax[mt], wf[0], wf[1],
                             acc[kind][mt][0][0], acc[kind][mt][0][1],
                             acc[kind][mt][0][2], acc[kind][mt][0][3]);
                    mma16816(acc[kind][mt][1], ax[mt], wf[2], wf[3],
                             acc[kind][mt][1][0], acc[kind][mt][1][1],
                             acc[kind][mt][1][2], acc[kind][mt][1][3]);
                }
            }
        }

        // Q -> registers (C-pair -> A-frag identity mapping, R14-proven)
        #pragma unroll
        for (int mt = 0; mt < 2; mt++) {
            qa[p * 2 + mt][0] = h2_of(acc[0][mt][0][0] * SCALE_EX2,
                                      acc[0][mt][0][1] * SCALE_EX2);
            qa[p * 2 + mt][1] = h2_of(acc[0][mt][0][2] * SCALE_EX2,
                                      acc[0][mt][0][3] * SCALE_EX2);
            qa[p * 2 + mt][2] = h2_of(acc[0][mt][1][0] * SCALE_EX2,
                                      acc[0][mt][1][1] * SCALE_EX2);
            qa[p * 2 + mt][3] = h2_of(acc[0][mt][1][2] * SCALE_EX2,
                                      acc[0][mt][1][3] * SCALE_EX2);
        }

        // K/V -> smem fp16, 48B rows
        const int g = lane >> 2, cq = (lane & 3) * 2;
        #pragma unroll
        for (int kind = 1; kind < 3; kind++) {
            char* base = smem + (kind == 1 ? OFF_K : OFF_V);
            #pragma unroll
            for (int mt = 0; mt < 2; mt++) {
                #pragma unroll
                for (int nt = 0; nt < 2; nt++) {
                    const int row = p * 256 + wid * 32 + mt * 16 + g;
                    const int eoff = (nt * 8 + cq) * 2;
                    *reinterpret_cast<uint32_t*>(base + row * 48 + eoff) =
                        h2_of(acc[kind][mt][nt][0], acc[kind][mt][nt][1]);
                    *reinterpret_cast<uint32_t*>(base + (row + 8) * 48 + eoff) =
                        h2_of(acc[kind][mt][nt][2], acc[kind][mt][nt][3]);
                }
            }
        }
    }
    __syncthreads();

    // ---- flash attention: warp owns 4 m16 tiles (64 rows) ----
    {
        float O[4][2][4], R[4][4];
        #pragma unroll
        for (int mt = 0; mt < 4; mt++) {
            #pragma unroll
            for (int nn = 0; nn < 2; nn++)
                #pragma unroll
                for (int j = 0; j < 4; j++) O[mt][nn][j] = 0.f;
            #pragma unroll
            for (int j = 0; j < 4; j++) R[mt][j] = 0.f;
        }

        const uint32_t koff = (uint32_t)(((lane & 7) + ((lane & 16) ? 8 : 0)) * 48
                                         + ((lane & 8) ? 16 : 0));
        const uint32_t voff = (uint32_t)(((lane & 7) + ((lane & 8) ? 8 : 0)) * 48
                                         + ((lane & 16) ? 16 : 0));

        #pragma unroll 2
        for (int kb = 0; kb < 32; kb++) {
            uint32_t kf[4], vf[4];
            ldm_x4 (kf, sbase + OFF_K + (uint32_t)kb * 768u + koff);
            ldm_x4t(vf, sbase + OFF_V + (uint32_t)kb * 768u + voff);

            #pragma unroll
            for (int mt = 0; mt < 4; mt++) {
                float s0[4], s1[4];
                mma16816(s0, qa[mt], kf[0], kf[1], NEG_BIAS, NEG_BIAS, NEG_BIAS, NEG_BIAS);
                mma16816(s1, qa[mt], kf[2], kf[3], NEG_BIAS, NEG_BIAS, NEG_BIAS, NEG_BIAS);
                uint32_t pa[4];
                pa[0] = h2sat(fast_ex2(s0[0]), fast_ex2(s0[1]));
                pa[1] = h2sat(fast_ex2(s0[2]), fast_ex2(s0[3]));
                pa[2] = h2sat(fast_ex2(s1[0]), fast_ex2(s1[1]));
                pa[3] = h2sat(fast_ex2(s1[2]), fast_ex2(s1[3]));
                mma16816(O[mt][0], pa, vf[0], vf[1],
                         O[mt][0][0], O[mt][0][1], O[mt][0][2], O[mt][0][3]);
                mma16816(O[mt][1], pa, vf[2], vf[3],
                         O[mt][1][0], O[mt][1][1], O[mt][1][2], O[mt][1][3]);
                mma16816(R[mt], pa, ONES2, ONES2,
                         R[mt][0], R[mt][1], R[mt][2], R[mt][3]);
            }
        }

        // normalize + write sx fp16 [512][24] (48B) into dead x region
        const int g = lane >> 2, cq = (lane & 3) * 2;
        #pragma unroll
        for (int mt = 0; mt < 4; mt++) {
            const int rowb = (mt >> 1) * 256 + wid * 32 + (mt & 1) * 16;
            const float inv0 = __frcp_rn(R[mt][0]);
            const float inv1 = __frcp_rn(R[mt][2]);
            const int row0 = rowb + g, row1 = rowb + g + 8;
            #pragma unroll
            for (int nn = 0; nn < 2; nn++) {
                const int eoff = (nn * 8 + cq) * 2;
                *reinterpret_cast<uint32_t*>(smem + OFF_SX + row0 * 48 + eoff) =
                    h2_of(O[mt][nn][0] * inv0, O[mt][nn][1] * inv0);
                *reinterpret_cast<uint32_t*>(smem + OFF_SX + row1 * 48 + eoff) =
                    h2_of(O[mt][nn][2] * inv1, O[mt][nn][3] * inv1);
            }
        }
    }
    __syncthreads();

    // ---- stage cls -> fp16 [32][520] into dead K/V ----
    for (int i = tid; i < C * N / 4; i += THREADS) {                // 16 iters
        const int c = i >> 7, n4 = i & 127;
        const float4 v4 = *reinterpret_cast<const float4*>(clsg + c * N + n4 * 4);
        *reinterpret_cast<uint2*>(smem + OFF_CLS + c * 1040 + n4 * 8) =
            make_uint2(h2_of(v4.x, v4.y), h2_of(v4.z, v4.w));
    }
    __syncthreads();

    // ---- pooling via mma on 8 warps: warp = (mt, nt, kgroup) ----
    {
        const int mt = wid & 1, nt = (wid >> 1) & 1, kg = wid >> 2;
        float acc[4] = {0.f, 0.f, 0.f, 0.f};
        const uint32_t aaddr = sbase + OFF_CLS
            + (uint32_t)(mt * 16 + (lane & 15)) * 1040u + (uint32_t)(lane >> 4) * 16u;
        const uint32_t brow = (uint32_t)((lane & 7) + ((lane & 8) ? 8 : 0));

        #pragma unroll
        for (int jj = 0; jj < 16; jj++) {
            const int j = kg * 16 + jj;
            uint32_t af[4];
            ldm_x4(af, aaddr + (uint32_t)j * 32u);
            uint32_t b0, b1;
            ldm_x2t(b0, b1, sbase + OFF_SX + ((uint32_t)j * 16u + brow) * 48u
                              + (uint32_t)nt * 16u);
            mma16816(acc, af, b0, b1, acc[0], acc[1], acc[2], acc[3]);
        }

        const int g = lane >> 2, cq = (lane & 3) * 2;
        float* part = smf + OFF_PART / 4;
        const int c0 = mt * 16 + g, d = nt * 8 + cq;
        *reinterpret_cast<float2*>(part + kg * 512 + c0 * 16 + d)       =
            make_float2(acc[0], acc[1]);
        *reinterpret_cast<float2*>(part + kg * 512 + (c0 + 8) * 16 + d) =
            make_float2(acc[2], acc[3]);
    }
    __syncthreads();

    // ---- final reduce: 256 threads, two (c,d) each ----
    {
        const float* part = smf + OFF_PART / 4;
        #pragma unroll
        for (int o = 0; o < 2; o++) {
            const int idx = tid + o * 256;
            const int c = idx >> 4, d = idx & 15;
            out[((size_t)bt * C + c) * HID + h * HD + d] =
                part[c * 16 + d] + part[512 + c * 16 + d];
        }
    }
}

extern "C" void kernel_launch(void* const* d_in, const int* in_sizes, int n_in,
                              void* d_out, int out_size) {
    const float* x   = (const float*)d_in[0];
    const float* cls = (const float*)d_in[1];
    const float* Wq  = (const float*)d_in[2];
    const float* Wk  = (const float*)d_in[3];
    const float* Wv  = (const float*)d_in[4];
    float* out = (float*)d_out;

    cudaFuncSetAttribute(spatial_attn_mma6, cudaFuncAttributeMaxDynamicSharedMemorySize,
                         SMEM_BYTES);
    spatial_attn_mma6<<<NBT * NH, THREADS, SMEM_BYTES>>>(x, cls, Wq, Wk, Wv, out);
}